// round 14
// baseline (speedup 1.0000x reference)
#include <cuda_runtime.h>
#include <cuda_bf16.h>
#include <cstdint>

// Problem constants (fixed by the reference setup)
#define B_    64
#define NA_   2048
#define EG_   40960             // directed edges per graph
#define E_    (B_ * EG_)        // 2,621,440 input edges
#define E2_   (2 * E_)          // 5,242,880 symmetrized edges

#define THREADS_  256
#define EPT_      2
#define C_        (THREADS_ * EPT_)   // 512 edges per chunk; EG_ % C_ == 0 (80 chunks/graph)
#define GRID_     (E_ / C_)           // 5120

// Output layout: tuple members flattened row-major and concatenated, cast to f32
#define BASE_EI   0
#define BASE_OFF  (2 * E2_)                 // 10,485,760
#define BASE_DIST (BASE_OFF + 3 * E2_)      // 26,214,400
#define BASE_VEC  (BASE_DIST + E2_)         // 31,457,280
#define BASE_NN   (BASE_VEC + 3 * E2_)      // 47,185,920
#define BASE_SWAP (BASE_NN + B_)            // 47,185,984

// Dynamic smem layout: [ float4 s_pos[NA_] | float stage[20*C_] ]
#define SM_POS_BYTES   (NA_ * 16)                 // 32768
#define SM_STAGE_FL    (20 * C_)                  // 10240 floats
#define SMEM_TOTAL     (SM_POS_BYTES + SM_STAGE_FL * 4)   // 73728 B -> 3 blocks/SM

// staging segment offsets (in floats): each segment is one contiguous global run
#define SG_EI0F  (0 * C_)
#define SG_EI1F  (1 * C_)
#define SG_EI0W  (2 * C_)
#define SG_EI1W  (3 * C_)
#define SG_OFFF  (4 * C_)    // 3C
#define SG_OFFW  (7 * C_)    // 3C
#define SG_DISTF (10 * C_)
#define SG_DISTW (11 * C_)
#define SG_VECF  (12 * C_)   // 3C
#define SG_VECW  (15 * C_)   // 3C
#define SG_SWPF  (18 * C_)
#define SG_SWPW  (19 * C_)

__device__ __forceinline__ uint32_t smem_u32(const void* p) {
    uint32_t a;
    asm("{ .reg .u64 t; cvta.to.shared.u64 t, %1; cvt.u32.u64 %0, t; }" : "=r"(a) : "l"(p));
    return a;
}

__device__ __forceinline__ void bulk_store(float* gdst, uint32_t ssrc, uint32_t bytes) {
    asm volatile("cp.async.bulk.global.shared::cta.bulk_group [%0], [%1], %2;"
                 :: "l"(gdst), "r"(ssrc), "r"(bytes) : "memory");
}

__global__ __launch_bounds__(THREADS_)
void graph_edges_kernel(const float* __restrict__ pos,
                        const float* __restrict__ cell,
                        const void*  __restrict__ ei_raw,
                        const int*   __restrict__ off,
                        const void*  __restrict__ nn_raw,
                        float*       __restrict__ out)
{
    extern __shared__ char smem[];
    float4* s_pos = (float4*)smem;
    float*  stg   = (float*)(smem + SM_POS_BYTES);
    __shared__ int s_is64;

    const int tid = threadIdx.x;
    const int blk = blockIdx.x;
    const int b     = blk / (EG_ / C_);   // graph id
    const int chunk = blk % (EG_ / C_);
    const int e0    = b * EG_ + chunk * C_;
    const int f0    = e0 + b * EG_;       // fwd run start (contiguous C_ slots)
    const int w0    = f0 + EG_;           // bwd run start

    // Per-block dtype detection (true int64 indices < 2^31; int32 data read
    // as u64 has a nonzero high half within the first 8 words w.o.p.)
    if (tid == 0) {
        const unsigned long long* eu = (const unsigned long long*)ei_raw;
        int is64 = 1;
        #pragma unroll
        for (int k = 0; k < 8; ++k)
            if (eu[k] >= (1ULL << 31)) { is64 = 0; break; }
        s_is64 = is64;
    }

    // Cooperative coalesced load of this graph's positions, padded to float4.
    {
        const float* pb = pos + (size_t)b * NA_ * 3;
        float* sp = (float*)s_pos;
        #pragma unroll
        for (int i = tid; i < NA_ * 3; i += THREADS_) {
            const int atom = i / 3;
            const int comp = i - atom * 3;
            sp[atom * 4 + comp] = pb[i];
        }
    }
    __syncthreads();
    const int is64 = s_is64;

    // cell[b] broadcast (L1-resident)
    const float* cb = cell + 9 * b;
    const float c00 = cb[0], c01 = cb[1], c02 = cb[2];
    const float c10 = cb[3], c11 = cb[4], c12 = cb[5];
    const float c20 = cb[6], c21 = cb[7], c22 = cb[8];

    const int abase = b * NA_;
    const int l = 2 * tid;                 // local slot (even)
    const int e = e0 + l;                  // edges e, e+1

    // ---- loads ----
    int iv0, jv0, iv1, jv1;
    if (is64) {
        const long long* ei = (const long long*)ei_raw;
        const longlong2 li = __ldcs((const longlong2*)(ei + e));
        const longlong2 lj = __ldcs((const longlong2*)(ei + E_ + e));
        iv0 = (int)li.x; iv1 = (int)li.y;
        jv0 = (int)lj.x; jv1 = (int)lj.y;
    } else {
        const int* ei = (const int*)ei_raw;
        const int2 li = __ldcs((const int2*)(ei + e));
        const int2 lj = __ldcs((const int2*)(ei + E_ + e));
        iv0 = li.x; iv1 = li.y;
        jv0 = lj.x; jv1 = lj.y;
    }
    const int2 oa = __ldcs((const int2*)(off + 3 * e));
    const int2 ob = __ldcs((const int2*)(off + 3 * e + 2));
    const int2 oc = __ldcs((const int2*)(off + 3 * e + 4));
    const float a0 = (float)oa.x, a1 = (float)oa.y, a2 = (float)ob.x;
    const float b0 = (float)ob.y, b1 = (float)oc.x, b2 = (float)oc.y;

    // ---- compute ----
    const float4 pi0 = s_pos[iv0 - abase];
    const float4 pj0 = s_pos[jv0 - abase];
    const float4 pi1 = s_pos[iv1 - abase];
    const float4 pj1 = s_pos[jv1 - abase];

    const float dx0 = pi0.x - pj0.x + (a0 * c00 + a1 * c10 + a2 * c20);
    const float dy0 = pi0.y - pj0.y + (a0 * c01 + a1 * c11 + a2 * c21);
    const float dz0 = pi0.z - pj0.z + (a0 * c02 + a1 * c12 + a2 * c22);
    const float d0  = sqrtf(dx0 * dx0 + dy0 * dy0 + dz0 * dz0);
    const float n0  = -1.0f / d0;
    const float vx0 = dx0 * n0, vy0 = dy0 * n0, vz0 = dz0 * n0;

    const float dx1 = pi1.x - pj1.x + (b0 * c00 + b1 * c10 + b2 * c20);
    const float dy1 = pi1.y - pj1.y + (b0 * c01 + b1 * c11 + b2 * c21);
    const float dz1 = pi1.z - pj1.z + (b0 * c02 + b1 * c12 + b2 * c22);
    const float d1  = sqrtf(dx1 * dx1 + dy1 * dy1 + dz1 * dz1);
    const float n1  = -1.0f / d1;
    const float vx1 = dx1 * n1, vy1 = dy1 * n1, vz1 = dz1 * n1;

    // ---- stage to smem (conflict-free contiguous STS) ----
    *(float2*)&stg[SG_EI0F + l] = make_float2((float)iv0, (float)iv1);
    *(float2*)&stg[SG_EI1F + l] = make_float2((float)jv0, (float)jv1);
    *(float2*)&stg[SG_EI0W + l] = make_float2((float)jv0, (float)jv1);
    *(float2*)&stg[SG_EI1W + l] = make_float2((float)iv0, (float)iv1);

    *(float2*)&stg[SG_OFFF + 3 * l]     = make_float2(a0, a1);
    *(float2*)&stg[SG_OFFF + 3 * l + 2] = make_float2(a2, b0);
    *(float2*)&stg[SG_OFFF + 3 * l + 4] = make_float2(b1, b2);
    *(float2*)&stg[SG_OFFW + 3 * l]     = make_float2(-a0, -a1);
    *(float2*)&stg[SG_OFFW + 3 * l + 2] = make_float2(-a2, -b0);
    *(float2*)&stg[SG_OFFW + 3 * l + 4] = make_float2(-b1, -b2);

    *(float2*)&stg[SG_DISTF + l] = make_float2(d0, d1);
    *(float2*)&stg[SG_DISTW + l] = make_float2(d0, d1);

    *(float2*)&stg[SG_VECF + 3 * l]     = make_float2(vx0, vy0);
    *(float2*)&stg[SG_VECF + 3 * l + 2] = make_float2(vz0, vx1);
    *(float2*)&stg[SG_VECF + 3 * l + 4] = make_float2(vy1, vz1);
    *(float2*)&stg[SG_VECW + 3 * l]     = make_float2(-vx0, -vy0);
    *(float2*)&stg[SG_VECW + 3 * l + 2] = make_float2(-vz0, -vx1);
    *(float2*)&stg[SG_VECW + 3 * l + 4] = make_float2(-vy1, -vz1);

    *(float2*)&stg[SG_SWPF + l] = make_float2((float)(w0 + l), (float)(w0 + l + 1));
    *(float2*)&stg[SG_SWPW + l] = make_float2((float)(f0 + l), (float)(f0 + l + 1));

    // num_neighbors_sym (block 0; tiny, via normal stores)
    if (blk == 0 && tid < B_) {
        long long v;
        if (is64) v = ((const long long*)nn_raw)[tid];
        else      v = (long long)((const int*)nn_raw)[tid];
        out[BASE_NN + tid] = (float)(2 * v);
    }

    __syncthreads();

    // ---- TMA bulk stores: smem -> global, bypassing per-thread STG path ----
    if (tid == 0) {
        asm volatile("fence.proxy.async.shared::cta;" ::: "memory");
        const uint32_t sb = smem_u32(stg);
        const uint32_t CB = C_ * 4;         // 2048 B
        bulk_store(out + BASE_EI + f0,        sb + SG_EI0F * 4, CB);
        bulk_store(out + BASE_EI + E2_ + f0,  sb + SG_EI1F * 4, CB);
        bulk_store(out + BASE_EI + w0,        sb + SG_EI0W * 4, CB);
        bulk_store(out + BASE_EI + E2_ + w0,  sb + SG_EI1W * 4, CB);
        bulk_store(out + BASE_OFF + 3 * f0,   sb + SG_OFFF * 4, 3 * CB);
        bulk_store(out + BASE_OFF + 3 * w0,   sb + SG_OFFW * 4, 3 * CB);
        bulk_store(out + BASE_DIST + f0,      sb + SG_DISTF * 4, CB);
        bulk_store(out + BASE_DIST + w0,      sb + SG_DISTW * 4, CB);
        bulk_store(out + BASE_VEC + 3 * f0,   sb + SG_VECF * 4, 3 * CB);
        bulk_store(out + BASE_VEC + 3 * w0,   sb + SG_VECW * 4, 3 * CB);
        bulk_store(out + BASE_SWAP + f0,      sb + SG_SWPF * 4, CB);
        bulk_store(out + BASE_SWAP + w0,      sb + SG_SWPW * 4, CB);
        asm volatile("cp.async.bulk.commit_group;" ::: "memory");
        asm volatile("cp.async.bulk.wait_group.read 0;" ::: "memory");
    }
}

extern "C" void kernel_launch(void* const* d_in, const int* in_sizes, int n_in,
                              void* d_out, int out_size) {
    const float* pos  = (const float*)d_in[0];   // [N,3] f32
    const float* cell = (const float*)d_in[1];   // [B,3,3] f32
    const void*  ei   = d_in[2];                 // [2,E] int64 or int32
    const int*   off  = (const int*)d_in[3];     // [E,3] int32
    const void*  nn   = d_in[4];                 // [B] int64 or int32
    float* out = (float*)d_out;

    cudaFuncSetAttribute(graph_edges_kernel,
                         cudaFuncAttributeMaxDynamicSharedMemorySize, SMEM_TOTAL);
    graph_edges_kernel<<<GRID_, THREADS_, SMEM_TOTAL>>>(pos, cell, ei, off, nn, out);
}

// round 15
// speedup vs baseline: 1.0713x; 1.0713x over previous
#include <cuda_runtime.h>
#include <cuda_bf16.h>
#include <cstdint>

// Problem constants (fixed by the reference setup)
#define B_    64
#define NA_   2048
#define EG_   40960             // directed edges per graph
#define E_    (B_ * EG_)        // 2,621,440 input edges
#define E2_   (2 * E_)          // 5,242,880 symmetrized edges

#define THREADS_  256
#define C_        256                 // edges per chunk (1 edge/thread/chunk)
#define BPG_      20                  // blocks per graph
#define CPB_      (EG_ / C_ / BPG_)   // 8 chunks per block
#define GRID_     (B_ * BPG_)         // 1280

// Output layout: tuple members flattened row-major and concatenated, cast to f32
#define BASE_EI   0
#define BASE_OFF  (2 * E2_)                 // 10,485,760
#define BASE_DIST (BASE_OFF + 3 * E2_)      // 26,214,400
#define BASE_VEC  (BASE_DIST + E2_)         // 31,457,280
#define BASE_NN   (BASE_VEC + 3 * E2_)      // 47,185,920
#define BASE_SWAP (BASE_NN + B_)            // 47,185,984

// Dynamic smem layout: [ float4 s_pos[NA_] | float stage[20*C_] ]
#define SM_POS_BYTES   (NA_ * 16)                         // 32768
#define SM_STAGE_FL    (20 * C_)                          // 5120 floats = 20480 B
#define SMEM_TOTAL     (SM_POS_BYTES + SM_STAGE_FL * 4)   // 53248 B -> 4 blocks/SM

// staging segment offsets (floats); each is one contiguous global run
#define SG_EI0F  (0 * C_)
#define SG_EI1F  (1 * C_)
#define SG_EI0W  (2 * C_)
#define SG_EI1W  (3 * C_)
#define SG_OFFF  (4 * C_)    // 3C
#define SG_OFFW  (7 * C_)    // 3C
#define SG_DISTF (10 * C_)
#define SG_DISTW (11 * C_)
#define SG_VECF  (12 * C_)   // 3C
#define SG_VECW  (15 * C_)   // 3C
#define SG_SWPF  (18 * C_)
#define SG_SWPW  (19 * C_)

__device__ __forceinline__ uint32_t smem_u32(const void* p) {
    uint32_t a;
    asm("{ .reg .u64 t; cvta.to.shared.u64 t, %1; cvt.u32.u64 %0, t; }" : "=r"(a) : "l"(p));
    return a;
}

__device__ __forceinline__ void bulk_store(float* gdst, uint32_t ssrc, uint32_t bytes) {
    asm volatile("cp.async.bulk.global.shared::cta.bulk_group [%0], [%1], %2;"
                 :: "l"(gdst), "r"(ssrc), "r"(bytes) : "memory");
}

__global__ __launch_bounds__(THREADS_, 4)
void graph_edges_kernel(const float* __restrict__ pos,
                        const float* __restrict__ cell,
                        const void*  __restrict__ ei_raw,
                        const int*   __restrict__ off,
                        const void*  __restrict__ nn_raw,
                        float*       __restrict__ out)
{
    extern __shared__ char smem[];
    float4* s_pos = (float4*)smem;
    float*  stg   = (float*)(smem + SM_POS_BYTES);
    __shared__ int s_is64;

    const int tid = threadIdx.x;
    const int blk = blockIdx.x;
    const int b   = blk / BPG_;             // graph id
    const int bg  = blk % BPG_;             // block index within graph

    // Per-block dtype detection (true int64 indices < 2^31; int32 data read
    // as u64 has a nonzero high half within the first 8 words w.o.p.)
    if (tid == 0) {
        const unsigned long long* eu = (const unsigned long long*)ei_raw;
        int is64 = 1;
        #pragma unroll
        for (int k = 0; k < 8; ++k)
            if (eu[k] >= (1ULL << 31)) { is64 = 0; break; }
        s_is64 = is64;
    }

    // Cooperative coalesced load of this graph's positions, padded to float4
    // (amortized over CPB_ chunks).
    {
        const float* pb = pos + (size_t)b * NA_ * 3;
        float* sp = (float*)s_pos;
        #pragma unroll
        for (int i = tid; i < NA_ * 3; i += THREADS_) {
            const int atom = i / 3;
            const int comp = i - atom * 3;
            sp[atom * 4 + comp] = pb[i];
        }
    }
    __syncthreads();
    const int is64 = s_is64;

    // cell[b] broadcast (L1-resident)
    const float* cb = cell + 9 * b;
    const float c00 = cb[0], c01 = cb[1], c02 = cb[2];
    const float c10 = cb[3], c11 = cb[4], c12 = cb[5];
    const float c20 = cb[6], c21 = cb[7], c22 = cb[8];

    const int abase = b * NA_;
    const uint32_t sb = smem_u32(stg);
    const uint32_t CB = C_ * 4;             // 1024 B per C_-float run

    // num_neighbors_sym (one block only; tiny)
    if (blk == 0 && tid < B_) {
        long long v;
        if (is64) v = ((const long long*)nn_raw)[tid];
        else      v = (long long)((const int*)nn_raw)[tid];
        out[BASE_NN + tid] = (float)(2 * v);
    }

    #pragma unroll 1
    for (int ci = 0; ci < CPB_; ++ci) {
        const int chunk = bg * CPB_ + ci;
        const int e0 = b * EG_ + chunk * C_;
        const int f0 = e0 + b * EG_;        // fwd run start (contiguous C_)
        const int w0 = f0 + EG_;            // bwd run start
        const int l  = tid;
        const int e  = e0 + l;

        // ---- loads + compute into registers (overlaps prior chunk's TMA) ----
        int iv, jv;
        if (is64) {
            const long long* ei = (const long long*)ei_raw;
            iv = (int)__ldcs(&ei[e]);
            jv = (int)__ldcs(&ei[E_ + e]);
        } else {
            const int* ei = (const int*)ei_raw;
            iv = __ldcs(&ei[e]);
            jv = __ldcs(&ei[E_ + e]);
        }
        const float f0f = (float)__ldcs(&off[3 * e + 0]);
        const float f1f = (float)__ldcs(&off[3 * e + 1]);
        const float f2f = (float)__ldcs(&off[3 * e + 2]);

        const float4 pi = s_pos[iv - abase];
        const float4 pj = s_pos[jv - abase];
        const float dx = pi.x - pj.x + (f0f * c00 + f1f * c10 + f2f * c20);
        const float dy = pi.y - pj.y + (f0f * c01 + f1f * c11 + f2f * c21);
        const float dz = pi.z - pj.z + (f0f * c02 + f1f * c12 + f2f * c22);
        const float dist = sqrtf(dx * dx + dy * dy + dz * dz);
        const float n = -1.0f / dist;
        const float vx = dx * n, vy = dy * n, vz = dz * n;

        // ---- staging buffer must be free of the previous chunk's TMA reads ----
        if (ci > 0) {
            if (tid == 0)
                asm volatile("cp.async.bulk.wait_group.read 0;" ::: "memory");
            __syncthreads();
        }

        // ---- stage to smem (conflict-free: stride-1 and stride-3 patterns) ----
        stg[SG_EI0F + l] = (float)iv;
        stg[SG_EI1F + l] = (float)jv;
        stg[SG_EI0W + l] = (float)jv;
        stg[SG_EI1W + l] = (float)iv;

        stg[SG_OFFF + 3 * l + 0] = f0f;
        stg[SG_OFFF + 3 * l + 1] = f1f;
        stg[SG_OFFF + 3 * l + 2] = f2f;
        stg[SG_OFFW + 3 * l + 0] = -f0f;
        stg[SG_OFFW + 3 * l + 1] = -f1f;
        stg[SG_OFFW + 3 * l + 2] = -f2f;

        stg[SG_DISTF + l] = dist;
        stg[SG_DISTW + l] = dist;

        stg[SG_VECF + 3 * l + 0] = vx;
        stg[SG_VECF + 3 * l + 1] = vy;
        stg[SG_VECF + 3 * l + 2] = vz;
        stg[SG_VECW + 3 * l + 0] = -vx;
        stg[SG_VECW + 3 * l + 1] = -vy;
        stg[SG_VECW + 3 * l + 2] = -vz;

        stg[SG_SWPF + l] = (float)(w0 + l);
        stg[SG_SWPW + l] = (float)(f0 + l);

        __syncthreads();

        // ---- TMA bulk stores: smem -> global (no per-thread STG path) ----
        if (tid == 0) {
            asm volatile("fence.proxy.async.shared::cta;" ::: "memory");
            bulk_store(out + BASE_EI + f0,        sb + SG_EI0F * 4, CB);
            bulk_store(out + BASE_EI + E2_ + f0,  sb + SG_EI1F * 4, CB);
            bulk_store(out + BASE_EI + w0,        sb + SG_EI0W * 4, CB);
            bulk_store(out + BASE_EI + E2_ + w0,  sb + SG_EI1W * 4, CB);
            bulk_store(out + BASE_OFF + 3 * f0,   sb + SG_OFFF * 4, 3 * CB);
            bulk_store(out + BASE_OFF + 3 * w0,   sb + SG_OFFW * 4, 3 * CB);
            bulk_store(out + BASE_DIST + f0,      sb + SG_DISTF * 4, CB);
            bulk_store(out + BASE_DIST + w0,      sb + SG_DISTW * 4, CB);
            bulk_store(out + BASE_VEC + 3 * f0,   sb + SG_VECF * 4, 3 * CB);
            bulk_store(out + BASE_VEC + 3 * w0,   sb + SG_VECW * 4, 3 * CB);
            bulk_store(out + BASE_SWAP + f0,      sb + SG_SWPF * 4, CB);
            bulk_store(out + BASE_SWAP + w0,      sb + SG_SWPW * 4, CB);
            asm volatile("cp.async.bulk.commit_group;" ::: "memory");
        }
        // No barrier here: next iteration's loads/compute don't touch stg;
        // the wait+barrier at its top protects the buffer reuse.
    }

    // Drain outstanding TMA smem reads before CTA teardown.
    if (tid == 0)
        asm volatile("cp.async.bulk.wait_group.read 0;" ::: "memory");
    __syncthreads();
}

extern "C" void kernel_launch(void* const* d_in, const int* in_sizes, int n_in,
                              void* d_out, int out_size) {
    const float* pos  = (const float*)d_in[0];   // [N,3] f32
    const float* cell = (const float*)d_in[1];   // [B,3,3] f32
    const void*  ei   = d_in[2];                 // [2,E] int64 or int32
    const int*   off  = (const int*)d_in[3];     // [E,3] int32
    const void*  nn   = d_in[4];                 // [B] int64 or int32
    float* out = (float*)d_out;

    cudaFuncSetAttribute(graph_edges_kernel,
                         cudaFuncAttributeMaxDynamicSharedMemorySize, SMEM_TOTAL);
    graph_edges_kernel<<<GRID_, THREADS_, SMEM_TOTAL>>>(pos, cell, ei, off, nn, out);
}

// round 16
// speedup vs baseline: 1.0731x; 1.0017x over previous
#include <cuda_runtime.h>
#include <cuda_bf16.h>
#include <cstdint>

// Problem constants (fixed by the reference setup)
#define B_    64
#define NA_   2048
#define EG_   40960             // directed edges per graph
#define E_    (B_ * EG_)        // 2,621,440 input edges
#define E2_   (2 * E_)          // 5,242,880 symmetrized edges

#define THREADS_  256
#define C_        256                 // edges per chunk (1 edge/thread/chunk)
#define BPG_      20                  // blocks per graph
#define CPB_      (EG_ / C_ / BPG_)   // 8 chunks per block
#define GRID_     (B_ * BPG_)         // 1280

// Output layout: tuple members flattened row-major and concatenated, cast to f32
#define BASE_EI   0
#define BASE_OFF  (2 * E2_)                 // 10,485,760
#define BASE_DIST (BASE_OFF + 3 * E2_)      // 26,214,400
#define BASE_VEC  (BASE_DIST + E2_)         // 31,457,280
#define BASE_NN   (BASE_VEC + 3 * E2_)      // 47,185,920
#define BASE_SWAP (BASE_NN + B_)            // 47,185,984

// Dynamic smem layout: [ float4 s_pos[NA_] | float stage[20*C_] ]
#define SM_POS_BYTES   (NA_ * 16)                         // 32768
#define SM_STAGE_FL    (20 * C_)                          // 5120 floats = 20480 B
#define SMEM_TOTAL     (SM_POS_BYTES + SM_STAGE_FL * 4)   // 53248 B -> 4 blocks/SM

// staging segment offsets (floats); each is one contiguous global run
#define SG_EI0F  (0 * C_)
#define SG_EI1F  (1 * C_)
#define SG_EI0W  (2 * C_)
#define SG_EI1W  (3 * C_)
#define SG_OFFF  (4 * C_)    // 3C
#define SG_OFFW  (7 * C_)    // 3C
#define SG_DISTF (10 * C_)
#define SG_DISTW (11 * C_)
#define SG_VECF  (12 * C_)   // 3C
#define SG_VECW  (15 * C_)   // 3C
#define SG_SWPF  (18 * C_)
#define SG_SWPW  (19 * C_)

__device__ __forceinline__ uint32_t smem_u32(const void* p) {
    uint32_t a;
    asm("{ .reg .u64 t; cvta.to.shared.u64 t, %1; cvt.u32.u64 %0, t; }" : "=r"(a) : "l"(p));
    return a;
}

__device__ __forceinline__ void bulk_store(float* gdst, uint32_t ssrc, uint32_t bytes) {
    asm volatile("cp.async.bulk.global.shared::cta.bulk_group [%0], [%1], %2;"
                 :: "l"(gdst), "r"(ssrc), "r"(bytes) : "memory");
}

__global__ __launch_bounds__(THREADS_, 4)
void graph_edges_kernel(const float* __restrict__ pos,
                        const float* __restrict__ cell,
                        const void*  __restrict__ ei_raw,
                        const int*   __restrict__ off,
                        const void*  __restrict__ nn_raw,
                        float*       __restrict__ out)
{
    extern __shared__ char smem[];
    float4* s_pos = (float4*)smem;
    float*  stg   = (float*)(smem + SM_POS_BYTES);
    __shared__ int s_is64;

    const int tid = threadIdx.x;
    const int blk = blockIdx.x;
    const int b   = blk / BPG_;             // graph id
    const int bg  = blk % BPG_;             // block index within graph

    // Per-block dtype detection (true int64 indices < 2^31; int32 data read
    // as u64 has a nonzero high half within the first 8 words w.o.p.)
    if (tid == 0) {
        const unsigned long long* eu = (const unsigned long long*)ei_raw;
        int is64 = 1;
        #pragma unroll
        for (int k = 0; k < 8; ++k)
            if (eu[k] >= (1ULL << 31)) { is64 = 0; break; }
        s_is64 = is64;
    }

    // Cooperative coalesced load of this graph's positions, padded to float4.
    {
        const float* pb = pos + (size_t)b * NA_ * 3;
        float* sp = (float*)s_pos;
        #pragma unroll
        for (int i = tid; i < NA_ * 3; i += THREADS_) {
            const int atom = i / 3;
            const int comp = i - atom * 3;
            sp[atom * 4 + comp] = pb[i];
        }
    }
    __syncthreads();
    const int is64 = s_is64;

    // cell[b] broadcast (L1-resident)
    const float* cb = cell + 9 * b;
    const float c00 = cb[0], c01 = cb[1], c02 = cb[2];
    const float c10 = cb[3], c11 = cb[4], c12 = cb[5];
    const float c20 = cb[6], c21 = cb[7], c22 = cb[8];

    const int abase = b * NA_;
    const uint32_t sb = smem_u32(stg);
    const uint32_t CB = C_ * 4;             // 1024 B per C_-float run
    const int l = tid;
    const int ebase = b * EG_ + bg * CPB_ * C_;   // first chunk's first edge

    // num_neighbors_sym (one block only; tiny)
    if (blk == 0 && tid < B_) {
        long long v;
        if (is64) v = ((const long long*)nn_raw)[tid];
        else      v = (long long)((const int*)nn_raw)[tid];
        out[BASE_NN + tid] = (float)(2 * v);
    }

    // ---- prefetch chunk 0 inputs ----
    int iv, jv;
    float o0, o1, o2;
    {
        const int e = ebase + l;
        if (is64) {
            const long long* ei = (const long long*)ei_raw;
            iv = (int)__ldcs(&ei[e]);
            jv = (int)__ldcs(&ei[E_ + e]);
        } else {
            const int* ei = (const int*)ei_raw;
            iv = __ldcs(&ei[e]);
            jv = __ldcs(&ei[E_ + e]);
        }
        o0 = (float)__ldcs(&off[3 * e + 0]);
        o1 = (float)__ldcs(&off[3 * e + 1]);
        o2 = (float)__ldcs(&off[3 * e + 2]);
    }

    #pragma unroll 1
    for (int ci = 0; ci < CPB_; ++ci) {
        const int e0 = ebase + ci * C_;
        const int f0 = e0 + b * EG_;        // fwd run start (contiguous C_)
        const int w0 = f0 + EG_;            // bwd run start

        // ---- compute from prefetched regs (LDS gathers; inputs landed long ago) ----
        const float4 pi = s_pos[iv - abase];
        const float4 pj = s_pos[jv - abase];
        const float dx = pi.x - pj.x + (o0 * c00 + o1 * c10 + o2 * c20);
        const float dy = pi.y - pj.y + (o0 * c01 + o1 * c11 + o2 * c21);
        const float dz = pi.z - pj.z + (o0 * c02 + o1 * c12 + o2 * c22);
        const float dist = sqrtf(dx * dx + dy * dy + dz * dz);
        const float n = -1.0f / dist;
        const float vx = dx * n, vy = dy * n, vz = dz * n;
        const float fiv = (float)iv, fjv = (float)jv;
        const float g0 = o0, g1 = o1, g2 = o2;

        // ---- staging buffer must be free of the previous chunk's TMA reads ----
        if (ci > 0) {
            if (tid == 0)
                asm volatile("cp.async.bulk.wait_group.read 0;" ::: "memory");
            __syncthreads();
        }

        // ---- stage to smem (stride-1 / stride-3, conflict-free) ----
        stg[SG_EI0F + l] = fiv;
        stg[SG_EI1F + l] = fjv;
        stg[SG_EI0W + l] = fjv;
        stg[SG_EI1W + l] = fiv;

        stg[SG_OFFF + 3 * l + 0] = g0;
        stg[SG_OFFF + 3 * l + 1] = g1;
        stg[SG_OFFF + 3 * l + 2] = g2;
        stg[SG_OFFW + 3 * l + 0] = -g0;
        stg[SG_OFFW + 3 * l + 1] = -g1;
        stg[SG_OFFW + 3 * l + 2] = -g2;

        stg[SG_DISTF + l] = dist;
        stg[SG_DISTW + l] = dist;

        stg[SG_VECF + 3 * l + 0] = vx;
        stg[SG_VECF + 3 * l + 1] = vy;
        stg[SG_VECF + 3 * l + 2] = vz;
        stg[SG_VECW + 3 * l + 0] = -vx;
        stg[SG_VECW + 3 * l + 1] = -vy;
        stg[SG_VECW + 3 * l + 2] = -vz;

        stg[SG_SWPF + l] = (float)(w0 + l);
        stg[SG_SWPW + l] = (float)(f0 + l);

        __syncthreads();

        // ---- TMA bulk stores: smem -> global (no per-thread STG path) ----
        if (tid == 0) {
            asm volatile("fence.proxy.async.shared::cta;" ::: "memory");
            bulk_store(out + BASE_EI + f0,        sb + SG_EI0F * 4, CB);
            bulk_store(out + BASE_EI + E2_ + f0,  sb + SG_EI1F * 4, CB);
            bulk_store(out + BASE_EI + w0,        sb + SG_EI0W * 4, CB);
            bulk_store(out + BASE_EI + E2_ + w0,  sb + SG_EI1W * 4, CB);
            bulk_store(out + BASE_OFF + 3 * f0,   sb + SG_OFFF * 4, 3 * CB);
            bulk_store(out + BASE_OFF + 3 * w0,   sb + SG_OFFW * 4, 3 * CB);
            bulk_store(out + BASE_DIST + f0,      sb + SG_DISTF * 4, CB);
            bulk_store(out + BASE_DIST + w0,      sb + SG_DISTW * 4, CB);
            bulk_store(out + BASE_VEC + 3 * f0,   sb + SG_VECF * 4, 3 * CB);
            bulk_store(out + BASE_VEC + 3 * w0,   sb + SG_VECW * 4, 3 * CB);
            bulk_store(out + BASE_SWAP + f0,      sb + SG_SWPF * 4, CB);
            bulk_store(out + BASE_SWAP + w0,      sb + SG_SWPW * 4, CB);
            asm volatile("cp.async.bulk.commit_group;" ::: "memory");
        }

        // ---- prefetch next chunk's inputs: a full chunk period to land ----
        if (ci + 1 < CPB_) {
            const int en = e0 + C_ + l;
            if (is64) {
                const long long* ei = (const long long*)ei_raw;
                iv = (int)__ldcs(&ei[en]);
                jv = (int)__ldcs(&ei[E_ + en]);
            } else {
                const int* ei = (const int*)ei_raw;
                iv = __ldcs(&ei[en]);
                jv = __ldcs(&ei[E_ + en]);
            }
            o0 = (float)__ldcs(&off[3 * en + 0]);
            o1 = (float)__ldcs(&off[3 * en + 1]);
            o2 = (float)__ldcs(&off[3 * en + 2]);
        }
    }

    // Drain outstanding TMA smem reads before CTA teardown.
    if (tid == 0)
        asm volatile("cp.async.bulk.wait_group.read 0;" ::: "memory");
    __syncthreads();
}

extern "C" void kernel_launch(void* const* d_in, const int* in_sizes, int n_in,
                              void* d_out, int out_size) {
    const float* pos  = (const float*)d_in[0];   // [N,3] f32
    const float* cell = (const float*)d_in[1];   // [B,3,3] f32
    const void*  ei   = d_in[2];                 // [2,E] int64 or int32
    const int*   off  = (const int*)d_in[3];     // [E,3] int32
    const void*  nn   = d_in[4];                 // [B] int64 or int32
    float* out = (float*)d_out;

    cudaFuncSetAttribute(graph_edges_kernel,
                         cudaFuncAttributeMaxDynamicSharedMemorySize, SMEM_TOTAL);
    graph_edges_kernel<<<GRID_, THREADS_, SMEM_TOTAL>>>(pos, cell, ei, off, nn, out);
}